// round 9
// baseline (speedup 1.0000x reference)
#include <cuda_runtime.h>
#include <cuda_fp16.h>
#include <cstdint>

// ===========================================================================
// Fused LSTM cell, mma.sync, 2 CTAs/SM. Warp grid 2(M) x 4(N): each warp
// owns 32 rows x 8 gate-cols of ONE chunk of the active pair (warpN>>1
// selects the chunk buffer) -> LDSM per k-step drops 40 -> 32 per CTA and
// per-warp accumulators halve. Pair-wise cp.async double buffering with
// deferred epilogue overlap (from R8). h -> smem fp16; output GEMM fused.
// d_out = [c | h | y], each B*128 fp32.
// ===========================================================================

#define AS_OFF    0
#define BS_OFF(i) (32768 + (i) * 32768)
#define HT_OFF    98304
#define SMEM_TOT  114688

__device__ __half g_W16r[512 * 256];    // gate-interleaved stacked weights, fp16
__device__ __half g_wout16[128 * 128];  // w_out, fp16

// --------------------------------------------------------------------------
// K0: convert weights. Chunk k (0..7), 64 rows:
//   [half0: z8,i8,f8,o8 | half1: z8,i8,f8,o8], half h covers gate-cols
//   [k*16 + h*8, +8). row r: grp=r>>5, gate=(r>>3)&3, sub=r&7.
// --------------------------------------------------------------------------
__global__ void prep_weights(const float* __restrict__ w,  const float* __restrict__ wi,
                             const float* __restrict__ wf, const float* __restrict__ wo,
                             const float* __restrict__ w_out)
{
    for (int idx = blockIdx.x * blockDim.x + threadIdx.x; idx < 512 * 256;
         idx += gridDim.x * blockDim.x) {
        int dstrow = idx >> 8, kk = idx & 255;
        int chunk = dstrow >> 6, r = dstrow & 63;
        int grp = r >> 5, gate = (r >> 3) & 3, sub = r & 7;
        int gc = chunk * 16 + grp * 8 + sub;
        const float* src = (gate == 0) ? w : (gate == 1) ? wi : (gate == 2) ? wf : wo;
        g_W16r[idx] = __float2half_rn(src[gc * 256 + kk]);
    }
    for (int idx = blockIdx.x * blockDim.x + threadIdx.x; idx < 128 * 128;
         idx += gridDim.x * blockDim.x)
        g_wout16[idx] = __float2half_rn(w_out[idx]);
}

// --------------------------------------------------------------------------
// helpers
// --------------------------------------------------------------------------
__device__ __forceinline__ void ldsm_x4(uint32_t addr, uint32_t& r0, uint32_t& r1,
                                        uint32_t& r2, uint32_t& r3)
{
    asm volatile("ldmatrix.sync.aligned.m8n8.x4.shared.b16 {%0,%1,%2,%3}, [%4];"
                 : "=r"(r0), "=r"(r1), "=r"(r2), "=r"(r3) : "r"(addr));
}
__device__ __forceinline__ void mma16816(float* c, const uint32_t* a, uint32_t b0, uint32_t b1)
{
    asm volatile(
        "mma.sync.aligned.m16n8k16.row.col.f32.f16.f16.f32 "
        "{%0,%1,%2,%3},{%4,%5,%6,%7},{%8,%9},{%0,%1,%2,%3};"
        : "+f"(c[0]), "+f"(c[1]), "+f"(c[2]), "+f"(c[3])
        : "r"(a[0]), "r"(a[1]), "r"(a[2]), "r"(a[3]), "r"(b0), "r"(b1));
}
__device__ __forceinline__ void cp16(uint32_t dst, const void* src)
{
    asm volatile("cp.async.cg.shared.global [%0], [%1], 16;" :: "r"(dst), "l"(src) : "memory");
}
__device__ __forceinline__ float tanha(float x) {
    float y; asm("tanh.approx.f32 %0, %1;" : "=f"(y) : "f"(x)); return y;
}
__device__ __forceinline__ float2 tanh2(float a, float b) {
    __half2 u = __floats2half2_rn(a, b);
    uint32_t uin = *(uint32_t*)&u, r;
    asm("tanh.approx.f16x2 %0, %1;" : "=r"(r) : "r"(uin));
    __half2 t = *(__half2*)&r;
    return make_float2(__half2float(t.x), __half2float(t.y));
}
__device__ __forceinline__ float2 sig2(float a, float b) {
    float2 t = tanh2(0.5f * a, 0.5f * b);
    return make_float2(fmaf(t.x, 0.5f, 0.5f), fmaf(t.y, 0.5f, 0.5f));
}
__device__ __forceinline__ uint32_t swz512(int r, int seg) {   // 512B rows, seg=16B
    return (uint32_t)(r * 512 + ((seg ^ (r & 7)) << 4));
}
__device__ __forceinline__ uint32_t swz256(int r, int seg) {   // 256B rows
    return (uint32_t)(r * 256 + ((seg ^ (r & 7)) << 4));
}

extern __shared__ char smem[];

// --------------------------------------------------------------------------
// Fused kernel. 256 threads = 8 warps in 2(M) x 4(N).
// warpM = warp>>2 (32-row M tile), warpN = warp&3;
// wbuf = warpN>>1 selects the pair-chunk, wh = warpN&1 the 8-col half.
// --------------------------------------------------------------------------
__global__ __launch_bounds__(256, 2) void lstm_fused(
    const float* __restrict__ x, const float* __restrict__ h_,
    const float* __restrict__ c_,
    const float* __restrict__ bz, const float* __restrict__ bi,
    const float* __restrict__ bf, const float* __restrict__ bo,
    const float* __restrict__ bout,
    float* __restrict__ outC, float* __restrict__ outH, float* __restrict__ outY)
{
    const int tid  = threadIdx.x, lane = tid & 31;
    const int warp = tid >> 5;
    const int warpM = warp >> 2, warpN = warp & 3;
    const int wbuf  = warpN >> 1, wh = warpN & 1;
    const int row0 = blockIdx.x * 64;

    const uint32_t sbase = (uint32_t)__cvta_generic_to_shared(smem);

    // ---- prologue: cp.async chunk pair 0 (chunks 0,1 -> Bs0,Bs1) ----
    for (int i = tid; i < 4096; i += 256) {
        int buf = i >> 11, r = (i >> 5) & 63, seg = i & 31;
        cp16(sbase + BS_OFF(buf) + swz512(r, seg),
             g_W16r + (size_t)buf * 16384 + r * 256 + seg * 8);
    }
    asm volatile("cp.async.commit_group;" ::: "memory");

    // ---- As: xh fp32 -> fp16 (cols 0-127 = x, 128-255 = h_) ----
    for (int i = tid; i < 2048; i += 256) {
        int r = i >> 5, seg = i & 31;
        const float* src = (seg < 16) ? (x  + (size_t)(row0 + r) * 128 + seg * 8)
                                      : (h_ + (size_t)(row0 + r) * 128 + (seg - 16) * 8);
        float4 v0 = ((const float4*)src)[0], v1 = ((const float4*)src)[1];
        __half2 h0 = __floats2half2_rn(v0.x, v0.y), h1 = __floats2half2_rn(v0.z, v0.w);
        __half2 h2 = __floats2half2_rn(v1.x, v1.y), h3 = __floats2half2_rn(v1.z, v1.w);
        uint4 pk;
        pk.x = *(uint32_t*)&h0; pk.y = *(uint32_t*)&h1;
        pk.z = *(uint32_t*)&h2; pk.w = *(uint32_t*)&h3;
        *(uint4*)(smem + AS_OFF + swz512(r, seg)) = pk;
    }

    // lane address components
    const int a_lrow = lane & 15;
    const int a_segk = lane >> 4;
    const int b_nloc = ((lane >> 4) & 1) * 8 + (lane & 7);
    const int b_segk = (lane >> 3) & 1;
    const int colq   = wh * 8 + 2 * (lane & 3);          // col within chunk's 16
    const int rq     = lane >> 2;                        // row-in-8 within M tile

    float accA[2][4][4], accB[2][4][4];                  // ping-pong (pair j / j-1)

    // ============= 4 iterations of chunk PAIRS =============
    #pragma unroll
    for (int j = 0; j < 4; j++) {
        float (*accC)[4][4] = (j & 1) ? accB : accA;     // current pair
        float (*accP)[4][4] = (j & 1) ? accA : accB;     // previous pair

        // ---- deferred epilogue of pair j-1 (overlaps pair j arrival) ----
        if (j > 0) {
            const int cc   = (j - 1) * 2 + wbuf;
            const int colb = cc * 16 + colq;
            const float2 vz = __ldg((const float2*)(bz + colb));
            const float2 vi = __ldg((const float2*)(bi + colb));
            const float2 vf = __ldg((const float2*)(bf + colb));
            const float2 vo = __ldg((const float2*)(bo + colb));
            const int hseg = cc * 2 + wh;
            #pragma unroll
            for (int mt = 0; mt < 2; mt++) {
                #pragma unroll
                for (int rh = 0; rh < 2; rh++) {
                    const int rloc = warpM * 32 + mt * 16 + rq + rh * 8;
                    const int row  = row0 + rloc;
                    const float2 cold = __ldg((const float2*)(c_ + (size_t)row * 128 + colb));
                    float2 z  = tanh2(accP[mt][0][rh*2+0] + vz.x, accP[mt][0][rh*2+1] + vz.y);
                    float2 si = sig2 (accP[mt][1][rh*2+0] + vi.x, accP[mt][1][rh*2+1] + vi.y);
                    float2 sf = sig2 (accP[mt][2][rh*2+0] + vf.x, accP[mt][2][rh*2+1] + vf.y);
                    float2 so = sig2 (accP[mt][3][rh*2+0] + vo.x, accP[mt][3][rh*2+1] + vo.y);
                    float c0 = fmaf(sf.x, cold.x, si.x * z.x);
                    float c1 = fmaf(sf.y, cold.y, si.y * z.y);
                    float h0 = so.x * tanha(c0);
                    float h1 = so.y * tanha(c1);
                    *(float2*)(outC + (size_t)row * 128 + colb) = make_float2(c0, c1);
                    *(float2*)(outH + (size_t)row * 128 + colb) = make_float2(h0, h1);
                    *(__half2*)(smem + HT_OFF + swz256(rloc, hseg) + (colb & 7) * 2) =
                        __floats2half2_rn(h0, h1);
                }
            }
        }

        asm volatile("cp.async.wait_group 0;" ::: "memory");   // pair j arrived
        __syncthreads();                                       // (covers As at j=0)

        #pragma unroll
        for (int mt = 0; mt < 2; mt++)
            #pragma unroll
            for (int g = 0; g < 4; g++)
                #pragma unroll
                for (int r = 0; r < 4; r++) accC[mt][g][r] = 0.f;

        // ---- MMA: each warp -> its chunk (wbuf), 32 rows x 8 cols x 4 gates ----
        const uint32_t as0 = sbase + AS_OFF;
        const uint32_t bsW = sbase + BS_OFF(wbuf);
        #pragma unroll
        for (int ks = 0; ks < 16; ks++) {
            uint32_t a[2][4];
            #pragma unroll
            for (int mt = 0; mt < 2; mt++)
                ldsm_x4(as0 + swz512(warpM * 32 + mt * 16 + a_lrow, ks * 2 + a_segk),
                        a[mt][0], a[mt][1], a[mt][2], a[mt][3]);
            uint32_t bb[2][4];                           // gp0: z,i  gp1: f,o
            #pragma unroll
            for (int gp = 0; gp < 2; gp++)
                ldsm_x4(bsW + swz512(wh * 32 + gp * 16 + b_nloc, ks * 2 + b_segk),
                        bb[gp][0], bb[gp][1], bb[gp][2], bb[gp][3]);
            #pragma unroll
            for (int g = 0; g < 4; g++) {
                const int gp = g >> 1, hi = g & 1;
                #pragma unroll
                for (int mt = 0; mt < 2; mt++)
                    mma16816(accC[mt][g], a[mt], bb[gp][hi * 2], bb[gp][hi * 2 + 1]);
            }
        }

        __syncthreads();   // all warps done reading Bs0/Bs1

        if (j < 3) {
            for (int i = tid; i < 4096; i += 256) {      // next pair
                int buf = i >> 11, r = (i >> 5) & 63, seg = i & 31;
                cp16(sbase + BS_OFF(buf) + swz512(r, seg),
                     g_W16r + (size_t)(2 * j + 2 + buf) * 16384 + r * 256 + seg * 8);
            }
        } else {
            for (int i = tid; i < 2048; i += 256) {      // w_out -> Bs0
                int r = i >> 4, seg = i & 15;
                cp16(sbase + BS_OFF(0) + swz256(r, seg), g_wout16 + r * 128 + seg * 8);
            }
        }
        asm volatile("cp.async.commit_group;" ::: "memory");
    }

    // ---- epilogue of pair 3 (accB holds it: j=3 -> accC=accB) ----
    {
        float (*accP)[4][4] = accB;
        const int cc   = 6 + wbuf;
        const int colb = cc * 16 + colq;
        const float2 vz = __ldg((const float2*)(bz + colb));
        const float2 vi = __ldg((const float2*)(bi + colb));
        const float2 vf = __ldg((const float2*)(bf + colb));
        const float2 vo = __ldg((const float2*)(bo + colb));
        const int hseg = cc * 2 + wh;
        #pragma unroll
        for (int mt = 0; mt < 2; mt++) {
            #pragma unroll
            for (int rh = 0; rh < 2; rh++) {
                const int rloc = warpM * 32 + mt * 16 + rq + rh * 8;
                const int row  = row0 + rloc;
                const float2 cold = __ldg((const float2*)(c_ + (size_t)row * 128 + colb));
                float2 z  = tanh2(accP[mt][0][rh*2+0] + vz.x, accP[mt][0][rh*2+1] + vz.y);
                float2 si = sig2 (accP[mt][1][rh*2+0] + vi.x, accP[mt][1][rh*2+1] + vi.y);
                float2 sf = sig2 (accP[mt][2][rh*2+0] + vf.x, accP[mt][2][rh*2+1] + vf.y);
                float2 so = sig2 (accP[mt][3][rh*2+0] + vo.x, accP[mt][3][rh*2+1] + vo.y);
                float c0 = fmaf(sf.x, cold.x, si.x * z.x);
                float c1 = fmaf(sf.y, cold.y, si.y * z.y);
                float h0 = so.x * tanha(c0);
                float h1 = so.y * tanha(c1);
                *(float2*)(outC + (size_t)row * 128 + colb) = make_float2(c0, c1);
                *(float2*)(outH + (size_t)row * 128 + colb) = make_float2(h0, h1);
                *(__half2*)(smem + HT_OFF + swz256(rloc, hseg) + (colb & 7) * 2) =
                    __floats2half2_rn(h0, h1);
            }
        }
    }

    asm volatile("cp.async.wait_group 0;" ::: "memory");   // w_out arrived
    __syncthreads();                                       // htile + w_out visible

    // =================== GEMM2: y = sigmoid(h @ w_out^T + b_out) ==========
    // warp tile: 32 rows x 32 cols (warpN*32).
    float acc2[2][4][4];
    #pragma unroll
    for (int mt = 0; mt < 2; mt++)
        #pragma unroll
        for (int g = 0; g < 4; g++)
            #pragma unroll
            for (int r = 0; r < 4; r++) acc2[mt][g][r] = 0.f;

    const uint32_t ht0 = sbase + HT_OFF;
    const uint32_t wo0 = sbase + BS_OFF(0);
    #pragma unroll
    for (int ks = 0; ks < 8; ks++) {
        uint32_t a[2][4];
        #pragma unroll
        for (int mt = 0; mt < 2; mt++)
            ldsm_x4(ht0 + swz256(warpM * 32 + mt * 16 + a_lrow, ks * 2 + a_segk),
                    a[mt][0], a[mt][1], a[mt][2], a[mt][3]);
        uint32_t bb[2][4];
        #pragma unroll
        for (int gp = 0; gp < 2; gp++)
            ldsm_x4(wo0 + swz256(warpN * 32 + gp * 16 + b_nloc, ks * 2 + b_segk),
                    bb[gp][0], bb[gp][1], bb[gp][2], bb[gp][3]);
        #pragma unroll
        for (int g = 0; g < 4; g++) {
            const int gp = g >> 1, hi = g & 1;
            #pragma unroll
            for (int mt = 0; mt < 2; mt++)
                mma16816(acc2[mt][g], a[mt], bb[gp][hi * 2], bb[gp][hi * 2 + 1]);
        }
    }

    #pragma unroll
    for (int g = 0; g < 4; g++) {
        const int col = warpN * 32 + g * 8 + 2 * (lane & 3);
        const float2 vb = __ldg((const float2*)(bout + col));
        #pragma unroll
        for (int mt = 0; mt < 2; mt++) {
            #pragma unroll
            for (int rh = 0; rh < 2; rh++) {
                const int row = row0 + warpM * 32 + mt * 16 + rq + rh * 8;
                float2 v = sig2(acc2[mt][g][rh * 2 + 0] + vb.x,
                                acc2[mt][g][rh * 2 + 1] + vb.y);
                *(float2*)(outY + (size_t)row * 128 + col) = v;
            }
        }
    }
}

// --------------------------------------------------------------------------
// Launch
// --------------------------------------------------------------------------
extern "C" void kernel_launch(void* const* d_in, const int* in_sizes, int n_in,
                              void* d_out, int out_size)
{
    const float* c_    = (const float*)d_in[0];
    const float* h_    = (const float*)d_in[1];
    const float* x     = (const float*)d_in[2];
    const float* w     = (const float*)d_in[3];
    const float* wi    = (const float*)d_in[4];
    const float* wf    = (const float*)d_in[5];
    const float* wo    = (const float*)d_in[6];
    const float* w_out = (const float*)d_in[7];
    const float* b     = (const float*)d_in[8];
    const float* bi    = (const float*)d_in[9];
    const float* bf    = (const float*)d_in[10];
    const float* bo    = (const float*)d_in[11];
    const float* b_out = (const float*)d_in[12];

    const int B = in_sizes[0] / 128;
    const size_t BC = (size_t)B * 128;
    float* outC = (float*)d_out;
    float* outH = outC + BC;
    float* outY = outH + BC;

    cudaFuncSetAttribute(lstm_fused, cudaFuncAttributeMaxDynamicSharedMemorySize, SMEM_TOT);

    prep_weights<<<64, 256>>>(w, wi, wf, wo, w_out);
    lstm_fused<<<B / 64, 256, SMEM_TOT>>>(x, h_, c_, b, bi, bf, bo, b_out,
                                          outC, outH, outY);
}

// round 10
// speedup vs baseline: 1.0364x; 1.0364x over previous
#include <cuda_runtime.h>
#include <cuda_fp16.h>
#include <cstdint>

// ===========================================================================
// Fused LSTM cell, mma.sync, 2 CTAs/SM, 2-chunk-interleaved MMA (R8 layout)
// with restructured schedule: c_ operands prefetched into registers BEFORE
// the MMA phase (latency hidden under 16 k-steps of HMMA), epilogue runs
// after the buffer-release sync so it overlaps the next pair's cp.async
// flight. Warp grid 4(M) x 2(N); warp tile 16x32 per chunk of the pair.
// d_out = [c | h | y], each B*128 fp32.
// ===========================================================================

#define AS_OFF    0
#define BS_OFF(i) (32768 + (i) * 32768)
#define HT_OFF    98304
#define SMEM_TOT  114688

__device__ __half g_W16r[512 * 256];    // gate-interleaved stacked weights, fp16
__device__ __half g_wout16[128 * 128];  // w_out, fp16

// --------------------------------------------------------------------------
// K0: convert weights. N-chunks of 64 rows:
//   chunk k (0..7): rows = [warpN0: z(8),i(8),f(8),o(8) | warpN1: same]
//   row r: grp=r>>5, gate=(r>>3)&3, sub=r&7 -> gate-col = k*16 + grp*8 + sub
// --------------------------------------------------------------------------
__global__ void prep_weights(const float* __restrict__ w,  const float* __restrict__ wi,
                             const float* __restrict__ wf, const float* __restrict__ wo,
                             const float* __restrict__ w_out)
{
    for (int idx = blockIdx.x * blockDim.x + threadIdx.x; idx < 512 * 256;
         idx += gridDim.x * blockDim.x) {
        int dstrow = idx >> 8, kk = idx & 255;
        int chunk = dstrow >> 6, r = dstrow & 63;
        int grp = r >> 5, gate = (r >> 3) & 3, sub = r & 7;
        int gc = chunk * 16 + grp * 8 + sub;
        const float* src = (gate == 0) ? w : (gate == 1) ? wi : (gate == 2) ? wf : wo;
        g_W16r[idx] = __float2half_rn(src[gc * 256 + kk]);
    }
    for (int idx = blockIdx.x * blockDim.x + threadIdx.x; idx < 128 * 128;
         idx += gridDim.x * blockDim.x)
        g_wout16[idx] = __float2half_rn(w_out[idx]);
}

// --------------------------------------------------------------------------
// helpers
// --------------------------------------------------------------------------
__device__ __forceinline__ void ldsm_x4(uint32_t addr, uint32_t& r0, uint32_t& r1,
                                        uint32_t& r2, uint32_t& r3)
{
    asm volatile("ldmatrix.sync.aligned.m8n8.x4.shared.b16 {%0,%1,%2,%3}, [%4];"
                 : "=r"(r0), "=r"(r1), "=r"(r2), "=r"(r3) : "r"(addr));
}
__device__ __forceinline__ void mma16816(float* c, const uint32_t* a, uint32_t b0, uint32_t b1)
{
    asm volatile(
        "mma.sync.aligned.m16n8k16.row.col.f32.f16.f16.f32 "
        "{%0,%1,%2,%3},{%4,%5,%6,%7},{%8,%9},{%0,%1,%2,%3};"
        : "+f"(c[0]), "+f"(c[1]), "+f"(c[2]), "+f"(c[3])
        : "r"(a[0]), "r"(a[1]), "r"(a[2]), "r"(a[3]), "r"(b0), "r"(b1));
}
__device__ __forceinline__ void cp16(uint32_t dst, const void* src)
{
    asm volatile("cp.async.cg.shared.global [%0], [%1], 16;" :: "r"(dst), "l"(src) : "memory");
}
__device__ __forceinline__ float tanha(float x) {
    float y; asm("tanh.approx.f32 %0, %1;" : "=f"(y) : "f"(x)); return y;
}
__device__ __forceinline__ float2 tanh2(float a, float b) {
    __half2 u = __floats2half2_rn(a, b);
    uint32_t uin = *(uint32_t*)&u, r;
    asm("tanh.approx.f16x2 %0, %1;" : "=r"(r) : "r"(uin));
    __half2 t = *(__half2*)&r;
    return make_float2(__half2float(t.x), __half2float(t.y));
}
__device__ __forceinline__ float2 sig2(float a, float b) {
    float2 t = tanh2(0.5f * a, 0.5f * b);
    return make_float2(fmaf(t.x, 0.5f, 0.5f), fmaf(t.y, 0.5f, 0.5f));
}
__device__ __forceinline__ uint32_t swz512(int r, int seg) {   // 512B rows, seg=16B
    return (uint32_t)(r * 512 + ((seg ^ (r & 7)) << 4));
}
__device__ __forceinline__ uint32_t swz256(int r, int seg) {   // 256B rows
    return (uint32_t)(r * 256 + ((seg ^ (r & 7)) << 4));
}

extern __shared__ char smem[];

// --------------------------------------------------------------------------
// Fused kernel. 256 threads = 8 warps in 4(M) x 2(N); warp tile 16x32/chunk.
// --------------------------------------------------------------------------
__global__ __launch_bounds__(256, 2) void lstm_fused(
    const float* __restrict__ x, const float* __restrict__ h_,
    const float* __restrict__ c_,
    const float* __restrict__ bz, const float* __restrict__ bi,
    const float* __restrict__ bf, const float* __restrict__ bo,
    const float* __restrict__ bout,
    float* __restrict__ outC, float* __restrict__ outH, float* __restrict__ outY)
{
    const int tid  = threadIdx.x, lane = tid & 31;
    const int warp = tid >> 5;
    const int warpM = warp >> 1, warpN = warp & 1;
    const int row0 = blockIdx.x * 64;

    const uint32_t sbase = (uint32_t)__cvta_generic_to_shared(smem);

    // ---- prologue: cp.async chunk pair 0 (chunks 0,1 -> Bs0,Bs1) ----
    for (int i = tid; i < 4096; i += 256) {
        int buf = i >> 11, r = (i >> 5) & 63, seg = i & 31;
        cp16(sbase + BS_OFF(buf) + swz512(r, seg),
             g_W16r + (size_t)buf * 16384 + r * 256 + seg * 8);
    }
    asm volatile("cp.async.commit_group;" ::: "memory");

    // ---- As: xh fp32 -> fp16 (cols 0-127 = x, 128-255 = h_) ----
    for (int i = tid; i < 2048; i += 256) {
        int r = i >> 5, seg = i & 31;
        const float* src = (seg < 16) ? (x  + (size_t)(row0 + r) * 128 + seg * 8)
                                      : (h_ + (size_t)(row0 + r) * 128 + (seg - 16) * 8);
        float4 v0 = ((const float4*)src)[0], v1 = ((const float4*)src)[1];
        __half2 h0 = __floats2half2_rn(v0.x, v0.y), h1 = __floats2half2_rn(v0.z, v0.w);
        __half2 h2 = __floats2half2_rn(v1.x, v1.y), h3 = __floats2half2_rn(v1.z, v1.w);
        uint4 pk;
        pk.x = *(uint32_t*)&h0; pk.y = *(uint32_t*)&h1;
        pk.z = *(uint32_t*)&h2; pk.w = *(uint32_t*)&h3;
        *(uint4*)(smem + AS_OFF + swz512(r, seg)) = pk;
    }

    // lane address components
    const int a_row  = warpM * 16 + (lane & 15);
    const int a_segk = (lane >> 4);
    const int b_nloc = ((lane >> 4) & 1) * 8 + (lane & 7);
    const int b_segk = (lane >> 3) & 1;
    const int colq   = warpN * 8 + 2 * (lane & 3);
    const int rbase  = warpM * 16 + (lane >> 2);

    float accA[4][4], accB[4][4];   // chunk 2j / 2j+1 accumulators

    // ============= 4 iterations of chunk PAIRS =============
    #pragma unroll
    for (int j = 0; j < 4; j++) {
        asm volatile("cp.async.wait_group 0;" ::: "memory");   // pair j arrived
        __syncthreads();                                       // (covers As at j=0)

        // ---- prefetch c_ for this pair's epilogue (consumed ~2500 cyc later) ----
        float2 cpre[2][2];                                     // [half][rh]
        #pragma unroll
        for (int half = 0; half < 2; half++) {
            const int colb = (j * 2 + half) * 16 + colq;
            #pragma unroll
            for (int rh = 0; rh < 2; rh++)
                cpre[half][rh] =
                    __ldg((const float2*)(c_ + (size_t)(row0 + rbase + rh * 8) * 128 + colb));
        }

        #pragma unroll
        for (int nt = 0; nt < 4; nt++)
            #pragma unroll
            for (int r = 0; r < 4; r++) { accA[nt][r] = 0.f; accB[nt][r] = 0.f; }

        // ---- interleaved MMA over both chunks: 8 independent acc chains ----
        const uint32_t as0 = sbase + AS_OFF;
        const uint32_t bs0 = sbase + BS_OFF(0);
        const uint32_t bs1 = sbase + BS_OFF(1);
        #pragma unroll
        for (int ks = 0; ks < 16; ks++) {
            uint32_t a[4];
            ldsm_x4(as0 + swz512(a_row, ks * 2 + a_segk), a[0], a[1], a[2], a[3]);
            uint32_t b0[2][4], b1[2][4];
            #pragma unroll
            for (int ntp = 0; ntp < 2; ntp++) {
                const uint32_t off = swz512(warpN * 32 + ntp * 16 + b_nloc, ks * 2 + b_segk);
                ldsm_x4(bs0 + off, b0[ntp][0], b0[ntp][1], b0[ntp][2], b0[ntp][3]);
                ldsm_x4(bs1 + off, b1[ntp][0], b1[ntp][1], b1[ntp][2], b1[ntp][3]);
            }
            #pragma unroll
            for (int nt = 0; nt < 4; nt++) {
                const int ntp = nt >> 1, hi = nt & 1;
                mma16816(accA[nt], a, b0[ntp][hi * 2], b0[ntp][hi * 2 + 1]);
                mma16816(accB[nt], a, b1[ntp][hi * 2], b1[ntp][hi * 2 + 1]);
            }
        }

        __syncthreads();   // all warps done reading Bs0/Bs1

        // ---- issue next pair's loads (flight covered by epilogue below) ----
        if (j < 3) {
            for (int i = tid; i < 4096; i += 256) {
                int buf = i >> 11, r = (i >> 5) & 63, seg = i & 31;
                cp16(sbase + BS_OFF(buf) + swz512(r, seg),
                     g_W16r + (size_t)(2 * j + 2 + buf) * 16384 + r * 256 + seg * 8);
            }
        } else {
            for (int i = tid; i < 2048; i += 256) {      // w_out -> Bs0
                int r = i >> 4, seg = i & 15;
                cp16(sbase + BS_OFF(0) + swz256(r, seg), g_wout16 + r * 128 + seg * 8);
            }
        }
        asm volatile("cp.async.commit_group;" ::: "memory");

        // ---- epilogue of pair j: registers + L1-hot biases + stores ----
        #pragma unroll
        for (int half = 0; half < 2; half++) {
            float (*acc)[4] = half ? accB : accA;
            const int cc   = j * 2 + half;
            const int colb = cc * 16 + colq;
            const float2 vz = __ldg((const float2*)(bz + colb));
            const float2 vi = __ldg((const float2*)(bi + colb));
            const float2 vf = __ldg((const float2*)(bf + colb));
            const float2 vo = __ldg((const float2*)(bo + colb));
            const int hseg = cc * 2 + warpN;
            #pragma unroll
            for (int rh = 0; rh < 2; rh++) {
                const int rloc = rbase + rh * 8;
                const int row  = row0 + rloc;
                const float2 cold = cpre[half][rh];
                float2 z  = tanh2(acc[0][rh*2+0] + vz.x, acc[0][rh*2+1] + vz.y);
                float2 si = sig2 (acc[1][rh*2+0] + vi.x, acc[1][rh*2+1] + vi.y);
                float2 sf = sig2 (acc[2][rh*2+0] + vf.x, acc[2][rh*2+1] + vf.y);
                float2 so = sig2 (acc[3][rh*2+0] + vo.x, acc[3][rh*2+1] + vo.y);
                float c0 = fmaf(sf.x, cold.x, si.x * z.x);
                float c1 = fmaf(sf.y, cold.y, si.y * z.y);
                float h0 = so.x * tanha(c0);
                float h1 = so.y * tanha(c1);
                *(float2*)(outC + (size_t)row * 128 + colb) = make_float2(c0, c1);
                *(float2*)(outH + (size_t)row * 128 + colb) = make_float2(h0, h1);
                *(__half2*)(smem + HT_OFF + swz256(rloc, hseg) + (colb & 7) * 2) =
                    __floats2half2_rn(h0, h1);
            }
        }
    }

    asm volatile("cp.async.wait_group 0;" ::: "memory");   // w_out arrived
    __syncthreads();                                       // htile + w_out visible

    // =================== GEMM2: y = sigmoid(h @ w_out^T + b_out) ==========
    float acc2[8][4];
    #pragma unroll
    for (int nt = 0; nt < 8; nt++)
        #pragma unroll
        for (int r = 0; r < 4; r++) acc2[nt][r] = 0.f;

    const uint32_t ht0 = sbase + HT_OFF;
    const uint32_t wo0 = sbase + BS_OFF(0);
    #pragma unroll
    for (int ks = 0; ks < 8; ks++) {
        uint32_t a[4];
        ldsm_x4(ht0 + swz256(warpM * 16 + (lane & 15), ks * 2 + a_segk), a[0], a[1], a[2], a[3]);
        uint32_t bb[4][4];
        #pragma unroll
        for (int ntp = 0; ntp < 4; ntp++)
            ldsm_x4(wo0 + swz256(warpN * 64 + ntp * 16 + b_nloc, ks * 2 + b_segk),
                    bb[ntp][0], bb[ntp][1], bb[ntp][2], bb[ntp][3]);
        #pragma unroll
        for (int nt = 0; nt < 8; nt++) {
            const int ntp = nt >> 1, hi = nt & 1;
            mma16816(acc2[nt], a, bb[ntp][hi * 2], bb[ntp][hi * 2 + 1]);
        }
    }

    #pragma unroll
    for (int nt = 0; nt < 8; nt++) {
        const int col = warpN * 64 + nt * 8 + 2 * (lane & 3);
        const float2 vb = __ldg((const float2*)(bout + col));
        #pragma unroll
        for (int rh = 0; rh < 2; rh++) {
            const int row = row0 + warpM * 16 + (lane >> 2) + rh * 8;
            float2 v = sig2(acc2[nt][rh * 2 + 0] + vb.x,
                            acc2[nt][rh * 2 + 1] + vb.y);
            *(float2*)(outY + (size_t)row * 128 + col) = v;
        }
    }
}

// --------------------------------------------------------------------------
// Launch
// --------------------------------------------------------------------------
extern "C" void kernel_launch(void* const* d_in, const int* in_sizes, int n_in,
                              void* d_out, int out_size)
{
    const float* c_    = (const float*)d_in[0];
    const float* h_    = (const float*)d_in[1];
    const float* x     = (const float*)d_in[2];
    const float* w     = (const float*)d_in[3];
    const float* wi    = (const float*)d_in[4];
    const float* wf    = (const float*)d_in[5];
    const float* wo    = (const float*)d_in[6];
    const float* w_out = (const float*)d_in[7];
    const float* b     = (const float*)d_in[8];
    const float* bi    = (const float*)d_in[9];
    const float* bf    = (const float*)d_in[10];
    const float* bo    = (const float*)d_in[11];
    const float* b_out = (const float*)d_in[12];

    const int B = in_sizes[0] / 128;
    const size_t BC = (size_t)B * 128;
    float* outC = (float*)d_out;
    float* outH = outC + BC;
    float* outY = outH + BC;

    cudaFuncSetAttribute(lstm_fused, cudaFuncAttributeMaxDynamicSharedMemorySize, SMEM_TOT);

    prep_weights<<<64, 256>>>(w, wi, wf, wo, w_out);
    lstm_fused<<<B / 64, 256, SMEM_TOT>>>(x, h_, c_, b, bi, bf, bo, b_out,
                                          outC, outH, outY);
}

// round 12
// speedup vs baseline: 1.1413x; 1.1013x over previous
#include <cuda_runtime.h>
#include <cuda_fp16.h>
#include <cstdint>

// ===========================================================================
// Fused LSTM cell, mma.sync, 2 CTAs/SM, 2-chunk-interleaved MMA.
// Weight movement via cp.async.bulk + mbarrier (DMA engine; zero per-thread
// LDGSTS issue cost). Weights stored PRE-SWIZZLED in gmem so the bulk copy is
// a flat byte copy producing the exact smem image the ldsm consumers expect.
// c_ prefetched into registers before the MMA phase; epilogue overlaps the
// next pair's bulk-copy flight. d_out = [c | h | y], each B*128 fp32.
// ===========================================================================

#define MBAR_OFF  0
#define AS_OFF    128
#define BS_OFF(i) (AS_OFF + 32768 + (i) * 32768)
#define HT_OFF    (AS_OFF + 98304)
#define SMEM_TOT  (HT_OFF + 16384)          // 114816

__device__ __half g_W16r[512 * 256];    // PRE-SWIZZLED gate weights (8 x 32KB chunks)
__device__ __half g_wout16[128 * 128];  // PRE-SWIZZLED w_out (32KB)

// --------------------------------------------------------------------------
// K0: build swizzled gmem images.
// Gates chunk c (64 rows x 512B): byte(r_local, seg16) at r*512+((seg^(r&7))<<4).
// Row r: grp=r>>5, gate=(r>>3)&3, sub=r&7 -> gate-col gc = c*16+grp*8+sub.
// w_out (128 rows x 256B): byte(r, seg16) at r*256+((seg^(r&7))<<4).
// --------------------------------------------------------------------------
__device__ __forceinline__ uint4 pack8f(const float* p) {
    float4 v0 = ((const float4*)p)[0], v1 = ((const float4*)p)[1];
    __half2 h0 = __floats2half2_rn(v0.x, v0.y), h1 = __floats2half2_rn(v0.z, v0.w);
    __half2 h2 = __floats2half2_rn(v1.x, v1.y), h3 = __floats2half2_rn(v1.z, v1.w);
    uint4 r;
    r.x = *(uint32_t*)&h0; r.y = *(uint32_t*)&h1;
    r.z = *(uint32_t*)&h2; r.w = *(uint32_t*)&h3;
    return r;
}

__global__ void prep_weights(const float* __restrict__ w,  const float* __restrict__ wi,
                             const float* __restrict__ wf, const float* __restrict__ wo,
                             const float* __restrict__ w_out)
{
    const int stride = gridDim.x * blockDim.x;
    for (int idx = blockIdx.x * blockDim.x + threadIdx.x; idx < 16384; idx += stride) {
        int c = idx >> 11, loc = idx & 2047;
        int r = loc >> 5, ss = loc & 31;
        int seg = ss ^ (r & 7);                    // un-swizzled K segment
        int grp = r >> 5, gate = (r >> 3) & 3, sub = r & 7;
        int gc = c * 16 + grp * 8 + sub;
        const float* src = (gate == 0) ? w : (gate == 1) ? wi : (gate == 2) ? wf : wo;
        ((uint4*)g_W16r)[idx] = pack8f(src + gc * 256 + seg * 8);
    }
    for (int idx = blockIdx.x * blockDim.x + threadIdx.x; idx < 2048; idx += stride) {
        int r = idx >> 4, ss = idx & 15;
        int seg = ss ^ (r & 7);
        ((uint4*)g_wout16)[idx] = pack8f(w_out + r * 128 + seg * 8);
    }
}

// --------------------------------------------------------------------------
// helpers
// --------------------------------------------------------------------------
__device__ __forceinline__ void ldsm_x4(uint32_t addr, uint32_t& r0, uint32_t& r1,
                                        uint32_t& r2, uint32_t& r3)
{
    asm volatile("ldmatrix.sync.aligned.m8n8.x4.shared.b16 {%0,%1,%2,%3}, [%4];"
                 : "=r"(r0), "=r"(r1), "=r"(r2), "=r"(r3) : "r"(addr));
}
__device__ __forceinline__ void mma16816(float* c, const uint32_t* a, uint32_t b0, uint32_t b1)
{
    asm volatile(
        "mma.sync.aligned.m16n8k16.row.col.f32.f16.f16.f32 "
        "{%0,%1,%2,%3},{%4,%5,%6,%7},{%8,%9},{%0,%1,%2,%3};"
        : "+f"(c[0]), "+f"(c[1]), "+f"(c[2]), "+f"(c[3])
        : "r"(a[0]), "r"(a[1]), "r"(a[2]), "r"(a[3]), "r"(b0), "r"(b1));
}
__device__ __forceinline__ void mbar_init(uint32_t a, uint32_t cnt) {
    asm volatile("mbarrier.init.shared.b64 [%0], %1;" :: "r"(a), "r"(cnt) : "memory");
}
__device__ __forceinline__ void mbar_expect_tx(uint32_t a, uint32_t bytes) {
    asm volatile("mbarrier.arrive.expect_tx.shared.b64 _, [%0], %1;" :: "r"(a), "r"(bytes) : "memory");
}
__device__ __forceinline__ void mbar_wait(uint32_t a, uint32_t parity) {
    asm volatile(
        "{\n\t.reg .pred P;\n\t"
        "WL%=:\n\t"
        "mbarrier.try_wait.parity.acquire.cta.shared::cta.b64 P, [%0], %1, 0x989680;\n\t"
        "@!P bra WL%=;\n\t}" :: "r"(a), "r"(parity) : "memory");
}
__device__ __forceinline__ void bulk_g2s(uint32_t dst, const void* src, uint32_t bytes, uint32_t mbar) {
    asm volatile("cp.async.bulk.shared::cta.global.mbarrier::complete_tx::bytes [%0], [%1], %2, [%3];"
                 :: "r"(dst), "l"(src), "r"(bytes), "r"(mbar) : "memory");
}
__device__ __forceinline__ float tanha(float x) {
    float y; asm("tanh.approx.f32 %0, %1;" : "=f"(y) : "f"(x)); return y;
}
__device__ __forceinline__ float2 tanh2(float a, float b) {
    __half2 u = __floats2half2_rn(a, b);
    uint32_t uin = *(uint32_t*)&u, r;
    asm("tanh.approx.f16x2 %0, %1;" : "=r"(r) : "r"(uin));
    __half2 t = *(__half2*)&r;
    return make_float2(__half2float(t.x), __half2float(t.y));
}
__device__ __forceinline__ float2 sig2(float a, float b) {
    float2 t = tanh2(0.5f * a, 0.5f * b);
    return make_float2(fmaf(t.x, 0.5f, 0.5f), fmaf(t.y, 0.5f, 0.5f));
}
__device__ __forceinline__ uint32_t swz512(int r, int seg) {   // 512B rows, seg=16B
    return (uint32_t)(r * 512 + ((seg ^ (r & 7)) << 4));
}
__device__ __forceinline__ uint32_t swz256(int r, int seg) {   // 256B rows
    return (uint32_t)(r * 256 + ((seg ^ (r & 7)) << 4));
}

extern __shared__ char smem[];

// --------------------------------------------------------------------------
// Fused kernel. 256 threads = 8 warps in 4(M) x 2(N); warp tile 16x32/chunk.
// --------------------------------------------------------------------------
__global__ __launch_bounds__(256, 2) void lstm_fused(
    const float* __restrict__ x, const float* __restrict__ h_,
    const float* __restrict__ c_,
    const float* __restrict__ bz, const float* __restrict__ bi,
    const float* __restrict__ bf, const float* __restrict__ bo,
    const float* __restrict__ bout,
    float* __restrict__ outC, float* __restrict__ outH, float* __restrict__ outY)
{
    const int tid  = threadIdx.x, lane = tid & 31;
    const int warp = tid >> 5;
    const int warpM = warp >> 1, warpN = warp & 1;
    const int row0 = blockIdx.x * 64;

    const uint32_t sbase = (uint32_t)__cvta_generic_to_shared(smem);
    const uint32_t mb = sbase + MBAR_OFF;

    if (tid == 0) mbar_init(mb, 1);
    __syncthreads();                               // mbar visible to all

    // ---- issue pair 0 bulk copy (DMA engine; zero per-thread cost) ----
    if (tid == 0) {
        mbar_expect_tx(mb, 65536);
        bulk_g2s(sbase + BS_OFF(0), (const char*)g_W16r,         32768, mb);
        bulk_g2s(sbase + BS_OFF(1), (const char*)g_W16r + 32768, 32768, mb);
    }

    // ---- As: xh fp32 -> fp16 (cols 0-127 = x, 128-255 = h_) ----
    for (int i = tid; i < 2048; i += 256) {
        int r = i >> 5, seg = i & 31;
        const float* src = (seg < 16) ? (x  + (size_t)(row0 + r) * 128 + seg * 8)
                                      : (h_ + (size_t)(row0 + r) * 128 + (seg - 16) * 8);
        uint4 pk = pack8f(src);
        *(uint4*)(smem + AS_OFF + swz512(r, seg)) = pk;
    }
    __syncthreads();                               // As visible

    // lane address components
    const int a_row  = warpM * 16 + (lane & 15);
    const int a_segk = (lane >> 4);
    const int b_nloc = ((lane >> 4) & 1) * 8 + (lane & 7);
    const int b_segk = (lane >> 3) & 1;
    const int colq   = warpN * 8 + 2 * (lane & 3);
    const int rbase  = warpM * 16 + (lane >> 2);

    float accA[4][4], accB[4][4];

    // ============= 4 iterations of chunk PAIRS =============
    #pragma unroll
    for (int j = 0; j < 4; j++) {
        mbar_wait(mb, j & 1);                      // pair j data ready (acquire)

        // ---- prefetch c_ (consumed ~2500 cyc later in the epilogue) ----
        float2 cpre[2][2];
        #pragma unroll
        for (int half = 0; half < 2; half++) {
            const int colb = (j * 2 + half) * 16 + colq;
            #pragma unroll
            for (int rh = 0; rh < 2; rh++)
                cpre[half][rh] =
                    __ldg((const float2*)(c_ + (size_t)(row0 + rbase + rh * 8) * 128 + colb));
        }

        #pragma unroll
        for (int nt = 0; nt < 4; nt++)
            #pragma unroll
            for (int r = 0; r < 4; r++) { accA[nt][r] = 0.f; accB[nt][r] = 0.f; }

        // ---- interleaved MMA over both chunks: 8 independent acc chains ----
        const uint32_t as0 = sbase + AS_OFF;
        const uint32_t bs0 = sbase + BS_OFF(0);
        const uint32_t bs1 = sbase + BS_OFF(1);
        #pragma unroll
        for (int ks = 0; ks < 16; ks++) {
            uint32_t a[4];
            ldsm_x4(as0 + swz512(a_row, ks * 2 + a_segk), a[0], a[1], a[2], a[3]);
            uint32_t b0[2][4], b1[2][4];
            #pragma unroll
            for (int ntp = 0; ntp < 2; ntp++) {
                const uint32_t off = swz512(warpN * 32 + ntp * 16 + b_nloc, ks * 2 + b_segk);
                ldsm_x4(bs0 + off, b0[ntp][0], b0[ntp][1], b0[ntp][2], b0[ntp][3]);
                ldsm_x4(bs1 + off, b1[ntp][0], b1[ntp][1], b1[ntp][2], b1[ntp][3]);
            }
            #pragma unroll
            for (int nt = 0; nt < 4; nt++) {
                const int ntp = nt >> 1, hi = nt & 1;
                mma16816(accA[nt], a, b0[ntp][hi * 2], b0[ntp][hi * 2 + 1]);
                mma16816(accB[nt], a, b1[ntp][hi * 2], b1[ntp][hi * 2 + 1]);
            }
        }

        __syncthreads();                           // all warps done reading Bs0/Bs1

        // ---- issue next loads (flight covered by epilogue) ----
        if (tid == 0) {
            if (j < 3) {
                mbar_expect_tx(mb, 65536);
                bulk_g2s(sbase + BS_OFF(0),
                         (const char*)g_W16r + (size_t)(2 * j + 2) * 32768, 32768, mb);
                bulk_g2s(sbase + BS_OFF(1),
                         (const char*)g_W16r + (size_t)(2 * j + 3) * 32768, 32768, mb);
            } else {
                mbar_expect_tx(mb, 32768);
                bulk_g2s(sbase + BS_OFF(0), (const char*)g_wout16, 32768, mb);
            }
        }

        // ---- epilogue of pair j: registers + L1-hot biases + stores ----
        #pragma unroll
        for (int half = 0; half < 2; half++) {
            float (*acc)[4] = half ? accB : accA;
            const int cc   = j * 2 + half;
            const int colb = cc * 16 + colq;
            const float2 vz = __ldg((const float2*)(bz + colb));
            const float2 vi = __ldg((const float2*)(bi + colb));
            const float2 vf = __ldg((const float2*)(bf + colb));
            const float2 vo = __ldg((const float2*)(bo + colb));
            const int hseg = cc * 2 + warpN;
            #pragma unroll
            for (int rh = 0; rh < 2; rh++) {
                const int rloc = rbase + rh * 8;
                const int row  = row0 + rloc;
                const float2 cold = cpre[half][rh];
                float2 z  = tanh2(acc[0][rh*2+0] + vz.x, acc[0][rh*2+1] + vz.y);
                float2 si = sig2 (acc[1][rh*2+0] + vi.x, acc[1][rh*2+1] + vi.y);
                float2 sf = sig2 (acc[2][rh*2+0] + vf.x, acc[2][rh*2+1] + vf.y);
                float2 so = sig2 (acc[3][rh*2+0] + vo.x, acc[3][rh*2+1] + vo.y);
                float c0 = fmaf(sf.x, cold.x, si.x * z.x);
                float c1 = fmaf(sf.y, cold.y, si.y * z.y);
                float h0 = so.x * tanha(c0);
                float h1 = so.y * tanha(c1);
                *(float2*)(outC + (size_t)row * 128 + colb) = make_float2(c0, c1);
                *(float2*)(outH + (size_t)row * 128 + colb) = make_float2(h0, h1);
                *(__half2*)(smem + HT_OFF + swz256(rloc, hseg) + (colb & 7) * 2) =
                    __floats2half2_rn(h0, h1);
            }
        }
    }

    mbar_wait(mb, 0);                              // w_out arrived (phase 4)
    __syncthreads();                               // htile visible

    // =================== GEMM2: y = sigmoid(h @ w_out^T + b_out) ==========
    float acc2[8][4];
    #pragma unroll
    for (int nt = 0; nt < 8; nt++)
        #pragma unroll
        for (int r = 0; r < 4; r++) acc2[nt][r] = 0.f;

    const uint32_t ht0 = sbase + HT_OFF;
    const uint32_t wo0 = sbase + BS_OFF(0);
    #pragma unroll
    for (int ks = 0; ks < 8; ks++) {
        uint32_t a[4];
        ldsm_x4(ht0 + swz256(warpM * 16 + (lane & 15), ks * 2 + a_segk), a[0], a[1], a[2], a[3]);
        uint32_t bb[4][4];
        #pragma unroll
        for (int ntp = 0; ntp < 4; ntp++)
            ldsm_x4(wo0 + swz256(warpN * 64 + ntp * 16 + b_nloc, ks * 2 + b_segk),
                    bb[ntp][0], bb[ntp][1], bb[ntp][2], bb[ntp][3]);
        #pragma unroll
        for (int nt = 0; nt < 8; nt++) {
            const int ntp = nt >> 1, hi = nt & 1;
            mma16816(acc2[nt], a, bb[ntp][hi * 2], bb[ntp][hi * 2 + 1]);
        }
    }

    #pragma unroll
    for (int nt = 0; nt < 8; nt++) {
        const int col = warpN * 64 + nt * 8 + 2 * (lane & 3);
        const float2 vb = __ldg((const float2*)(bout + col));
        #pragma unroll
        for (int rh = 0; rh < 2; rh++) {
            const int row = row0 + warpM * 16 + (lane >> 2) + rh * 8;
            float2 v = sig2(acc2[nt][rh * 2 + 0] + vb.x,
                            acc2[nt][rh * 2 + 1] + vb.y);
            *(float2*)(outY + (size_t)row * 128 + col) = v;
        }
    }
}

// --------------------------------------------------------------------------
// Launch
// --------------------------------------------------------------------------
extern "C" void kernel_launch(void* const* d_in, const int* in_sizes, int n_in,
                              void* d_out, int out_size)
{
    const float* c_    = (const float*)d_in[0];
    const float* h_    = (const float*)d_in[1];
    const float* x     = (const float*)d_in[2];
    const float* w     = (const float*)d_in[3];
    const float* wi    = (const float*)d_in[4];
    const float* wf    = (const float*)d_in[5];
    const float* wo    = (const float*)d_in[6];
    const float* w_out = (const float*)d_in[7];
    const float* b     = (const float*)d_in[8];
    const float* bi    = (const float*)d_in[9];
    const float* bf    = (const float*)d_in[10];
    const float* bo    = (const float*)d_in[11];
    const float* b_out = (const float*)d_in[12];

    const int B = in_sizes[0] / 128;
    const size_t BC = (size_t)B * 128;
    float* outC = (float*)d_out;
    float* outH = outC + BC;
    float* outY = outH + BC;

    cudaFuncSetAttribute(lstm_fused, cudaFuncAttributeMaxDynamicSharedMemorySize, SMEM_TOT);

    prep_weights<<<64, 256>>>(w, wi, wf, wo, w_out);
    lstm_fused<<<B / 64, 256, SMEM_TOT>>>(x, h_, c_, b, bi, bf, bo, b_out,
                                          outC, outH, outY);
}

// round 14
// speedup vs baseline: 1.1682x; 1.0236x over previous
#include <cuda_runtime.h>
#include <cuda_fp16.h>
#include <cstdint>

// ===========================================================================
// Fused LSTM cell, mma.sync, 2 CTAs/SM. Warp grid 2(M) x 4(N): each warp owns
// 32 rows x 8 gate-cols of ONE chunk of the active pair (warpN>>1 selects the
// chunk buffer) -> B-fragment ldsm duplication halves (L1 wavefronts -15%).
// Weight movement via cp.async.bulk + mbarrier (pre-swizzled gmem image).
// c_ prefetched before MMA; epilogue overlaps next pair's bulk flight.
// Streaming (.cs) hints on one-touch global traffic.
// d_out = [c | h | y], each B*128 fp32.
// ===========================================================================

#define MBAR_OFF  0
#define AS_OFF    128
#define BS_OFF(i) (AS_OFF + 32768 + (i) * 32768)
#define HT_OFF    (AS_OFF + 98304)
#define SMEM_TOT  (HT_OFF + 16384)          // 114816

__device__ __half g_W16r[512 * 256];    // PRE-SWIZZLED gate weights (8 x 32KB chunks)
__device__ __half g_wout16[128 * 128];  // PRE-SWIZZLED w_out (32KB)

// --------------------------------------------------------------------------
// K0: build swizzled gmem images.
// Gates chunk c (64 rows x 512B): byte(r, seg16) at r*512+((seg^(r&7))<<4).
// Row r: grp=r>>5, gate=(r>>3)&3, sub=r&7 -> gate-col gc = c*16+grp*8+sub.
// (chunk col-halves: wh=grp -> cols c*16+wh*8..+8)
// w_out (128 rows x 256B): byte(r, seg16) at r*256+((seg^(r&7))<<4).
// --------------------------------------------------------------------------
__device__ __forceinline__ uint4 pack8f(const float* p) {
    float4 v0 = ((const float4*)p)[0], v1 = ((const float4*)p)[1];
    __half2 h0 = __floats2half2_rn(v0.x, v0.y), h1 = __floats2half2_rn(v0.z, v0.w);
    __half2 h2 = __floats2half2_rn(v1.x, v1.y), h3 = __floats2half2_rn(v1.z, v1.w);
    uint4 r;
    r.x = *(uint32_t*)&h0; r.y = *(uint32_t*)&h1;
    r.z = *(uint32_t*)&h2; r.w = *(uint32_t*)&h3;
    return r;
}

__global__ void prep_weights(const float* __restrict__ w,  const float* __restrict__ wi,
                             const float* __restrict__ wf, const float* __restrict__ wo,
                             const float* __restrict__ w_out)
{
    const int stride = gridDim.x * blockDim.x;
    for (int idx = blockIdx.x * blockDim.x + threadIdx.x; idx < 16384; idx += stride) {
        int c = idx >> 11, loc = idx & 2047;
        int r = loc >> 5, ss = loc & 31;
        int seg = ss ^ (r & 7);                    // un-swizzled K segment
        int grp = r >> 5, gate = (r >> 3) & 3, sub = r & 7;
        int gc = c * 16 + grp * 8 + sub;
        const float* src = (gate == 0) ? w : (gate == 1) ? wi : (gate == 2) ? wf : wo;
        ((uint4*)g_W16r)[idx] = pack8f(src + gc * 256 + seg * 8);
    }
    for (int idx = blockIdx.x * blockDim.x + threadIdx.x; idx < 2048; idx += stride) {
        int r = idx >> 4, ss = idx & 15;
        int seg = ss ^ (r & 7);
        ((uint4*)g_wout16)[idx] = pack8f(w_out + r * 128 + seg * 8);
    }
}

// --------------------------------------------------------------------------
// helpers
// --------------------------------------------------------------------------
__device__ __forceinline__ void ldsm_x4(uint32_t addr, uint32_t& r0, uint32_t& r1,
                                        uint32_t& r2, uint32_t& r3)
{
    asm volatile("ldmatrix.sync.aligned.m8n8.x4.shared.b16 {%0,%1,%2,%3}, [%4];"
                 : "=r"(r0), "=r"(r1), "=r"(r2), "=r"(r3) : "r"(addr));
}
__device__ __forceinline__ void mma16816(float* c, const uint32_t* a, uint32_t b0, uint32_t b1)
{
    asm volatile(
        "mma.sync.aligned.m16n8k16.row.col.f32.f16.f16.f32 "
        "{%0,%1,%2,%3},{%4,%5,%6,%7},{%8,%9},{%0,%1,%2,%3};"
        : "+f"(c[0]), "+f"(c[1]), "+f"(c[2]), "+f"(c[3])
        : "r"(a[0]), "r"(a[1]), "r"(a[2]), "r"(a[3]), "r"(b0), "r"(b1));
}
__device__ __forceinline__ void mbar_init(uint32_t a, uint32_t cnt) {
    asm volatile("mbarrier.init.shared.b64 [%0], %1;" :: "r"(a), "r"(cnt) : "memory");
}
__device__ __forceinline__ void mbar_expect_tx(uint32_t a, uint32_t bytes) {
    asm volatile("mbarrier.arrive.expect_tx.shared.b64 _, [%0], %1;" :: "r"(a), "r"(bytes) : "memory");
}
__device__ __forceinline__ void mbar_wait(uint32_t a, uint32_t parity) {
    asm volatile(
        "{\n\t.reg .pred P;\n\t"
        "WL%=:\n\t"
        "mbarrier.try_wait.parity.acquire.cta.shared::cta.b64 P, [%0], %1, 0x989680;\n\t"
        "@!P bra WL%=;\n\t}" :: "r"(a), "r"(parity) : "memory");
}
__device__ __forceinline__ void bulk_g2s(uint32_t dst, const void* src, uint32_t bytes, uint32_t mbar) {
    asm volatile("cp.async.bulk.shared::cta.global.mbarrier::complete_tx::bytes [%0], [%1], %2, [%3];"
                 :: "r"(dst), "l"(src), "r"(bytes), "r"(mbar) : "memory");
}
__device__ __forceinline__ float tanha(float x) {
    float y; asm("tanh.approx.f32 %0, %1;" : "=f"(y) : "f"(x)); return y;
}
__device__ __forceinline__ float2 tanh2(float a, float b) {
    __half2 u = __floats2half2_rn(a, b);
    uint32_t uin = *(uint32_t*)&u, r;
    asm("tanh.approx.f16x2 %0, %1;" : "=r"(r) : "r"(uin));
    __half2 t = *(__half2*)&r;
    return make_float2(__half2float(t.x), __half2float(t.y));
}
__device__ __forceinline__ float2 sig2(float a, float b) {
    float2 t = tanh2(0.5f * a, 0.5f * b);
    return make_float2(fmaf(t.x, 0.5f, 0.5f), fmaf(t.y, 0.5f, 0.5f));
}
__device__ __forceinline__ uint32_t swz512(int r, int seg) {   // 512B rows, seg=16B
    return (uint32_t)(r * 512 + ((seg ^ (r & 7)) << 4));
}
__device__ __forceinline__ uint32_t swz256(int r, int seg) {   // 256B rows
    return (uint32_t)(r * 256 + ((seg ^ (r & 7)) << 4));
}

extern __shared__ char smem[];

// --------------------------------------------------------------------------
// Fused kernel. 256 threads = 8 warps in 2(M) x 4(N).
// warpM = warp>>2 (32-row M tile), warpN = warp&3;
// wbuf = warpN>>1 selects the pair-chunk buffer, wh = warpN&1 the 8-col half.
// --------------------------------------------------------------------------
__global__ __launch_bounds__(256, 2) void lstm_fused(
    const float* __restrict__ x, const float* __restrict__ h_,
    const float* __restrict__ c_,
    const float* __restrict__ bz, const float* __restrict__ bi,
    const float* __restrict__ bf, const float* __restrict__ bo,
    const float* __restrict__ bout,
    float* __restrict__ outC, float* __restrict__ outH, float* __restrict__ outY)
{
    const int tid  = threadIdx.x, lane = tid & 31;
    const int warp = tid >> 5;
    const int warpM = warp >> 2, warpN = warp & 3;
    const int wbuf  = warpN >> 1, wh = warpN & 1;
    const int row0 = blockIdx.x * 64;

    const uint32_t sbase = (uint32_t)__cvta_generic_to_shared(smem);
    const uint32_t mb = sbase + MBAR_OFF;

    if (tid == 0) mbar_init(mb, 1);
    __syncthreads();                               // mbar visible to all

    // ---- issue pair 0 bulk copy (DMA engine) ----
    if (tid == 0) {
        mbar_expect_tx(mb, 65536);
        bulk_g2s(sbase + BS_OFF(0), (const char*)g_W16r,         32768, mb);
        bulk_g2s(sbase + BS_OFF(1), (const char*)g_W16r + 32768, 32768, mb);
    }

    // ---- As: xh fp32 -> fp16 (cols 0-127 = x, 128-255 = h_) ----
    for (int i = tid; i < 2048; i += 256) {
        int r = i >> 5, seg = i & 31;
        const float* src = (seg < 16) ? (x  + (size_t)(row0 + r) * 128 + seg * 8)
                                      : (h_ + (size_t)(row0 + r) * 128 + (seg - 16) * 8);
        uint4 pk = pack8f(src);
        *(uint4*)(smem + AS_OFF + swz512(r, seg)) = pk;
    }
    __syncthreads();                               // As visible

    // lane address components
    const int a_lrow = lane & 15;
    const int a_segk = lane >> 4;
    const int b_nloc = ((lane >> 4) & 1) * 8 + (lane & 7);
    const int b_segk = (lane >> 3) & 1;
    const int colq   = wh * 8 + 2 * (lane & 3);    // col within chunk's 16
    const int rq     = lane >> 2;

    float acc[2][4][4];

    // ============= 4 iterations of chunk PAIRS =============
    #pragma unroll
    for (int j = 0; j < 4; j++) {
        mbar_wait(mb, j & 1);                      // pair j data ready (acquire)

        const int cc   = j * 2 + wbuf;             // this warp's chunk
        const int colb = cc * 16 + colq;

        // ---- prefetch c_ (consumed ~2500 cyc later) ----
        float2 cpre[2][2];                         // [mt][rh]
        #pragma unroll
        for (int mt = 0; mt < 2; mt++)
            #pragma unroll
            for (int rh = 0; rh < 2; rh++)
                cpre[mt][rh] = __ldcs((const float2*)(
                    c_ + (size_t)(row0 + warpM * 32 + mt * 16 + rq + rh * 8) * 128 + colb));

        #pragma unroll
        for (int mt = 0; mt < 2; mt++)
            #pragma unroll
            for (int g = 0; g < 4; g++)
                #pragma unroll
                for (int r = 0; r < 4; r++) acc[mt][g][r] = 0.f;

        // ---- MMA: warp covers 32 rows x 8 cols x 4 gates of its chunk ----
        const uint32_t as0 = sbase + AS_OFF;
        const uint32_t bsW = sbase + BS_OFF(wbuf);
        #pragma unroll
        for (int ks = 0; ks < 16; ks++) {
            uint32_t a[2][4];
            #pragma unroll
            for (int mt = 0; mt < 2; mt++)
                ldsm_x4(as0 + swz512(warpM * 32 + mt * 16 + a_lrow, ks * 2 + a_segk),
                        a[mt][0], a[mt][1], a[mt][2], a[mt][3]);
            uint32_t bb[2][4];                     // gp0: z,i   gp1: f,o
            #pragma unroll
            for (int gp = 0; gp < 2; gp++)
                ldsm_x4(bsW + swz512(wh * 32 + gp * 16 + b_nloc, ks * 2 + b_segk),
                        bb[gp][0], bb[gp][1], bb[gp][2], bb[gp][3]);
            #pragma unroll
            for (int g = 0; g < 4; g++) {
                const int gp = g >> 1, hi = g & 1;
                #pragma unroll
                for (int mt = 0; mt < 2; mt++)
                    mma16816(acc[mt][g], a[mt], bb[gp][hi * 2], bb[gp][hi * 2 + 1]);
            }
        }

        __syncthreads();                           // all warps done reading Bs0/Bs1

        // ---- issue next loads (flight covered by epilogue) ----
        if (tid == 0) {
            if (j < 3) {
                mbar_expect_tx(mb, 65536);
                bulk_g2s(sbase + BS_OFF(0),
                         (const char*)g_W16r + (size_t)(2 * j + 2) * 32768, 32768, mb);
                bulk_g2s(sbase + BS_OFF(1),
                         (const char*)g_W16r + (size_t)(2 * j + 3) * 32768, 32768, mb);
            } else {
                mbar_expect_tx(mb, 32768);
                bulk_g2s(sbase + BS_OFF(0), (const char*)g_wout16, 32768, mb);
            }
        }

        // ---- epilogue of chunk cc ----
        {
            const float2 vz = __ldg((const float2*)(bz + colb));
            const float2 vi = __ldg((const float2*)(bi + colb));
            const float2 vf = __ldg((const float2*)(bf + colb));
            const float2 vo = __ldg((const float2*)(bo + colb));
            const int hseg = cc * 2 + wh;
            #pragma unroll
            for (int mt = 0; mt < 2; mt++) {
                #pragma unroll
                for (int rh = 0; rh < 2; rh++) {
                    const int rloc = warpM * 32 + mt * 16 + rq + rh * 8;
                    const int row  = row0 + rloc;
                    const float2 cold = cpre[mt][rh];
                    float2 z  = tanh2(acc[mt][0][rh*2+0] + vz.x, acc[mt][0][rh*2+1] + vz.y);
                    float2 si = sig2 (acc[mt][1][rh*2+0] + vi.x, acc[mt][1][rh*2+1] + vi.y);
                    float2 sf = sig2 (acc[mt][2][rh*2+0] + vf.x, acc[mt][2][rh*2+1] + vf.y);
                    float2 so = sig2 (acc[mt][3][rh*2+0] + vo.x, acc[mt][3][rh*2+1] + vo.y);
                    float c0 = fmaf(sf.x, cold.x, si.x * z.x);
                    float c1 = fmaf(sf.y, cold.y, si.y * z.y);
                    float h0 = so.x * tanha(c0);
                    float h1 = so.y * tanha(c1);
                    __stcs((float2*)(outC + (size_t)row * 128 + colb), make_float2(c0, c1));
                    __stcs((float2*)(outH + (size_t)row * 128 + colb), make_float2(h0, h1));
                    *(__half2*)(smem + HT_OFF + swz256(rloc, hseg) + (colb & 7) * 2) =
                        __floats2half2_rn(h0, h1);
                }
            }
        }
    }

    mbar_wait(mb, 0);                              // w_out arrived (phase 4)
    __syncthreads();                               // htile visible

    // =================== GEMM2: y = sigmoid(h @ w_out^T + b_out) ==========
    // warp tile: 32 rows x 32 cols.
    float acc2[2][4][4];
    #pragma unroll
    for (int mt = 0; mt < 2; mt++)
        #pragma unroll
        for (int g = 0; g < 4; g++)
            #pragma unroll
            for (int r = 0; r < 4; r++) acc2[mt][g][r] = 0.f;

    const uint32_t ht0 = sbase + HT_OFF;
    const uint32_t wo0 = sbase + BS_OFF(0);
    #pragma unroll
    for (int ks = 0; ks < 8; ks++) {
        uint32_t a[2][4];
        #pragma unroll
        for (int mt = 0; mt < 2; mt++)
            ldsm_x4(ht0 + swz256(warpM * 32 + mt * 16 + a_lrow, ks * 2 + a_segk),
                    a[mt][0], a[mt][1], a[mt][2], a[mt][3]);
        uint32_t bb[2][4];
        #pragma unroll
        for (int gp = 0; gp < 2; gp++)
            ldsm_x4(wo0 + swz256(warpN * 32 + gp * 16 + b_nloc, ks * 2 + b_segk),
                    bb[gp][0], bb[gp][1], bb[gp][2], bb[gp][3]);
        #pragma unroll
        for (int g = 0; g < 4; g++) {
            const int gp = g >> 1, hi = g & 1;
            #pragma unroll
            for (int mt = 0; mt < 2; mt++)
                mma16816(acc2[mt][g], a[mt], bb[gp][hi * 2], bb[gp][hi * 2 + 1]);
        }
    }

    #pragma unroll
    for (int g = 0; g < 4; g++) {
        const int col = warpN * 32 + g * 8 + 2 * (lane & 3);
        const float2 vb = __ldg((const float2*)(bout + col));
        #pragma unroll
        for (int mt = 0; mt < 2; mt++) {
            #pragma unroll
            for (int rh = 0; rh < 2; rh++) {
                const int row = row0 + warpM * 32 + mt * 16 + rq + rh * 8;
                float2 v = sig2(acc2[mt][g][rh * 2 + 0] + vb.x,
                                acc2[mt][g][rh * 2 + 1] + vb.y);
                __stcs((float2*)(outY + (size_t)row * 128 + col), v);
            }
        }
    }
}

// --------------------------------------------------------------------------
// Launch
// --------------------------------------------------------------------------
extern "C" void kernel_launch(void* const* d_in, const int* in_sizes, int n_in,
                              void* d_out, int out_size)
{
    const float* c_    = (const float*)d_in[0];
    const float* h_    = (const float*)d_in[1];
    const float* x     = (const float*)d_in[2];
    const float* w     = (const float*)d_in[3];
    const float* wi    = (const float*)d_in[4];
    const float* wf    = (const float*)d_in[5];
    const float* wo    = (const float*)d_in[6];
    const float* w_out = (const float*)d_in[7];
    const float* b     = (const float*)d_in[8];
    const float* bi    = (const float*)d_in[9];
    const float* bf    = (const float*)d_in[10];
    const float* bo    = (const float*)d_in[11];
    const float* b_out = (const float*)d_in[12];

    const int B = in_sizes[0] / 128;
    const size_t BC = (size_t)B * 128;
    float* outC = (float*)d_out;
    float* outH = outC + BC;
    float* outY = outH + BC;

    cudaFuncSetAttribute(lstm_fused, cudaFuncAttributeMaxDynamicSharedMemorySize, SMEM_TOT);

    prep_weights<<<64, 256>>>(w, wi, wf, wo, w_out);
    lstm_fused<<<B / 64, 256, SMEM_TOT>>>(x, h_, c_, b, bi, bf, bo, b_out,
                                          outC, outH, outY);
}